// round 7
// baseline (speedup 1.0000x reference)
#include <cuda_runtime.h>
#include <cuda_fp16.h>
#include <cstdint>
#include <math.h>

// ---------------------------------------------------------------------------
// CrossModalFusion, fp16 mma.sync (m16n8k16, f32 acc).
// R7: BN=256 wide-tile variant for attention GEMMs, half scores, fused k|v.
// B=32, Sr=Sp=2048, D=400, H=512
// ---------------------------------------------------------------------------
#define B_   32
#define SR_  2048
#define SP_  2048
#define DIM_ 400
#define HID_ 512
#define MROWS (B_ * SR_)          // 65536

__device__ __half g_q [(size_t)MROWS * HID_];
__device__ __half g_k [(size_t)MROWS * HID_];
__device__ __half g_vt[(size_t)MROWS * HID_];     // [B][H][Sp]
__device__ __half g_sh[(size_t)B_ * SR_ * SP_];   // 256 MB scores (half)
__device__ __half g_ph[(size_t)B_ * SR_ * SP_];   // 256 MB probs (half)
__device__ __half g_o [(size_t)MROWS * HID_];
__device__ float  g_p [(size_t)MROWS * DIM_];
__device__ __half g_wt[4 * 512 * 400];            // WqT | WkT | WvT | WpT
__device__ __half g_rgbh [(size_t)MROWS * DIM_];
__device__ __half g_poseh[(size_t)MROWS * DIM_];

__device__ __forceinline__ uint32_t smem_u32(const void* p) {
    uint32_t a;
    asm("{ .reg .u64 t; cvta.to.shared.u64 t, %1; cvt.u32.u64 %0, t; }" : "=r"(a) : "l"(p));
    return a;
}
__device__ __forceinline__ void cp16(uint32_t dst, const void* src, int bytes) {
    asm volatile("cp.async.cg.shared.global [%0], [%1], 16, %2;"
                 :: "r"(dst), "l"(src), "r"(bytes));
}
#define LDSM_X4(r0, r1, r2, r3, addr)                                         \
    asm volatile("ldmatrix.sync.aligned.m8n8.x4.shared.b16 {%0,%1,%2,%3}, [%4];" \
                 : "=r"(r0), "=r"(r1), "=r"(r2), "=r"(r3) : "r"(addr))

#define MMA_F16(c, a0, a1, a2, a3, b0, b1)                                    \
    asm volatile("mma.sync.aligned.m16n8k16.row.col.f32.f16.f16.f32 "         \
                 "{%0,%1,%2,%3}, {%4,%5,%6,%7}, {%8,%9}, {%0,%1,%2,%3};"      \
                 : "+f"((c)[0]), "+f"((c)[1]), "+f"((c)[2]), "+f"((c)[3])     \
                 : "r"(a0), "r"(a1), "r"(a2), "r"(a3), "r"(b0), "r"(b1))

// ---------------------------------------------------------------------------
// fp16 GEMM: C[M,N] = alpha*A[M,K]@B[N,K]^T (+bias), f32 acc.
// CTA tile 128 x BN (BN in {128,256}); 8 warps, warp tile 64 x (BN/4).
// BK=64 halves, 3-stage cp.async.
// MODE 0: plain store (OUT_HALF: half2 vs float2).
// MODE 2: fused k|v — n0<512: k store (half, ld 512, bias=bk);
//         n0>=512: vT store via smem staging (half, bias2=bv).
// ---------------------------------------------------------------------------
template <int BN, int MODE, int OUT_HALF>
__global__ __launch_bounds__(256, BN == 128 ? 2 : 1)
void h16_mma_gemm(const __half* __restrict__ A, const __half* __restrict__ Bm,
                  const float* __restrict__ bias, const float* __restrict__ bias2,
                  void* __restrict__ Cv, __half* __restrict__ C2,
                  int N, int K,
                  long long sA, long long sB, long long sC, float alpha)
{
    constexpr int N16 = BN / 64;       // B ldsm.x4 per warp per k16
    constexpr uint32_t STAGE = 16384u + (uint32_t)BN * 128u;

    extern __shared__ char smem[];
    const uint32_t sb = smem_u32(smem);
    const int tid = threadIdx.x;
    const int wid = tid >> 5, lane = tid & 31;
    const int warp_m = wid & 1;                 // m offset 0/64
    const int warp_n = wid >> 1;                // n offset k*(BN/4)

    A  += (long long)blockIdx.z * sA;
    Bm += (long long)blockIdx.z * sB;
    const int m0 = blockIdx.y * 128;
    const int n0 = blockIdx.x * BN;
    const int KT = (K + 63) >> 6;

    auto load_stage = [&](int kt, int s) {
        const int k0 = kt << 6;
        const uint32_t base = sb + (uint32_t)s * STAGE;
#pragma unroll
        for (int i = 0; i < 4; i++) {            // A: 128 rows x 8 chunks
            int e = tid + (i << 8);
            int row = e >> 3, c = e & 7;
            int kk = k0 + (c << 3);
            uint32_t off = (uint32_t)(row * 128) + (uint32_t)((c ^ (row & 7)) << 4);
            const bool kin = kk < K;
            const __half* ga = A + (long long)(m0 + row) * K + kk;
            cp16(base + off, ga, kin ? 16 : 0);
        }
#pragma unroll
        for (int i = 0; i < BN / 32; i++) {      // B: BN rows x 8 chunks
            int e = tid + (i << 8);
            int row = e >> 3, c = e & 7;
            int kk = k0 + (c << 3);
            uint32_t off = (uint32_t)(row * 128) + (uint32_t)((c ^ (row & 7)) << 4);
            const bool bin = (kk < K) && (n0 + row) < N;
            const __half* gb = Bm + (long long)(n0 + row) * K + kk;
            cp16(base + 16384u + off, bin ? gb : Bm, bin ? 16 : 0);
        }
        asm volatile("cp.async.commit_group;" ::: "memory");
    };

    float acc[4][2 * N16][4];
#pragma unroll
    for (int i = 0; i < 4; i++)
#pragma unroll
        for (int j = 0; j < 2 * N16; j++)
#pragma unroll
            for (int k = 0; k < 4; k++) acc[i][j][k] = 0.f;

    const int t = lane >> 3, r = lane & 7;
    const uint32_t a_row = (uint32_t)(warp_m * 64 + (t & 1) * 8 + r);
    const uint32_t b_row = (uint32_t)(warp_n * (BN / 4) + (t & 1) * 8 + r);
    const uint32_t chb   = (uint32_t)(t >> 1);

    load_stage(0, 0);
    if (KT > 1) load_stage(1, 1);

    for (int kt = 0; kt < KT; kt++) {
        if (kt + 1 < KT) asm volatile("cp.async.wait_group 1;" ::: "memory");
        else             asm volatile("cp.async.wait_group 0;" ::: "memory");
        __syncthreads();
        if (kt + 2 < KT) load_stage(kt + 2, (kt + 2) % 3);

        const uint32_t baseA = sb + (uint32_t)(kt % 3) * STAGE;
        const uint32_t baseB = baseA + 16384u;

#pragma unroll
        for (int ks = 0; ks < 4; ks++) {
            uint32_t a[4][4], b[N16][4];
#pragma unroll
            for (int mi = 0; mi < 4; mi++) {
                uint32_t addr = baseA + (a_row + mi * 16) * 128u
                              + ((((ks * 2) + chb) ^ (uint32_t)r) << 4);
                LDSM_X4(a[mi][0], a[mi][1], a[mi][2], a[mi][3], addr);
            }
#pragma unroll
            for (int j = 0; j < N16; j++) {
                uint32_t addr = baseB + (b_row + j * 16) * 128u
                              + ((((ks * 2) + chb) ^ (uint32_t)r) << 4);
                LDSM_X4(b[j][0], b[j][1], b[j][2], b[j][3], addr);
            }
#pragma unroll
            for (int mi = 0; mi < 4; mi++)
#pragma unroll
                for (int ni = 0; ni < 2 * N16; ni++)
                    MMA_F16(acc[mi][ni], a[mi][0], a[mi][1], a[mi][2], a[mi][3],
                            b[ni >> 1][ni & 1], b[ni >> 1][(ni & 1) + 2]);
        }
    }

    const int m_base_l = warp_m * 64;
    const int n_base_l = warp_n * (BN / 4);
    const int row_in = lane >> 2;
    const int col_in = (lane & 3) * 2;

    const bool k_side = (MODE != 2) || (n0 < 512);

    if (MODE == 0 || (MODE == 2 && k_side)) {
        const int ldC = (MODE == 2) ? 512 : N;
#pragma unroll
        for (int mi = 0; mi < 4; mi++) {
            const int gm0 = m0 + m_base_l + mi * 16 + row_in;
#pragma unroll
            for (int ni = 0; ni < 2 * N16; ni++) {
                const int gn = n0 + n_base_l + ni * 8 + col_in;
                if (gn < N) {
                    float b0 = bias ? __ldg(&bias[gn]) : 0.f;
                    float b1 = bias ? __ldg(&bias[gn + 1]) : 0.f;
                    float v00 = acc[mi][ni][0] * alpha + b0;
                    float v01 = acc[mi][ni][1] * alpha + b1;
                    float v10 = acc[mi][ni][2] * alpha + b0;
                    float v11 = acc[mi][ni][3] * alpha + b1;
                    if (OUT_HALF) {
                        __half* C = (__half*)Cv + (long long)blockIdx.z * sC;
                        *reinterpret_cast<__half2*>(&C[(long long)gm0 * ldC + gn]) =
                            __floats2half2_rn(v00, v01);
                        *reinterpret_cast<__half2*>(&C[(long long)(gm0 + 8) * ldC + gn]) =
                            __floats2half2_rn(v10, v11);
                    } else {
                        float* C = (float*)Cv + (long long)blockIdx.z * sC;
                        *reinterpret_cast<float2*>(&C[(long long)gm0 * ldC + gn]) =
                            make_float2(v00, v01);
                        *reinterpret_cast<float2*>(&C[(long long)(gm0 + 8) * ldC + gn]) =
                            make_float2(v10, v11);
                    }
                }
            }
        }
    } else {
        // v side: vT[b][h][p], h = gn - 512. Stage [n][m] half tile in smem.
        __syncthreads();
        __half* sm = reinterpret_cast<__half*>(smem);
        const int PAD = 136;
        const int h0 = n0 - 512;
#pragma unroll
        for (int mi = 0; mi < 4; mi++) {
            const int ml = m_base_l + mi * 16 + row_in;
#pragma unroll
            for (int ni = 0; ni < 2 * N16; ni++) {
                const int nl = n_base_l + ni * 8 + col_in;
                float b0 = bias2 ? __ldg(&bias2[h0 + nl]) : 0.f;
                float b1 = bias2 ? __ldg(&bias2[h0 + nl + 1]) : 0.f;
                sm[nl * PAD + ml]           = __float2half_rn(acc[mi][ni][0] + b0);
                sm[(nl + 1) * PAD + ml]     = __float2half_rn(acc[mi][ni][1] + b1);
                sm[nl * PAD + ml + 8]       = __float2half_rn(acc[mi][ni][2] + b0);
                sm[(nl + 1) * PAD + ml + 8] = __float2half_rn(acc[mi][ni][3] + b1);
            }
        }
        __syncthreads();
        const long long obase = ((long long)(m0 >> 11) << 20) + (m0 & 2047);
#pragma unroll
        for (int pass = 0; pass < 8; pass++) {
            int chunk = pass * 256 + tid;        // 128 n x 16 m-chunks
            int n = chunk >> 4;
            int mc = (chunk & 15) << 3;
            uint4 v = *reinterpret_cast<uint4*>(&sm[n * PAD + mc]);
            *reinterpret_cast<uint4*>(&C2[obase + ((long long)(h0 + n) << 11) + mc]) = v;
        }
    }
}

// ---------------------------------------------------------------------------
// rgb & pose -> half copies
// ---------------------------------------------------------------------------
__global__ __launch_bounds__(256)
void prep_half(const float* __restrict__ rgb, const float* __restrict__ pose,
               __half* __restrict__ rgbh, __half* __restrict__ poseh)
{
    const long long NEL4 = (long long)MROWS * DIM_ / 4;
    long long idx = (long long)blockIdx.x * 256 + threadIdx.x;
    const float* src; __half* dst; long long j;
    if (idx < NEL4)          { src = rgb;  dst = rgbh;  j = idx; }
    else if (idx < 2 * NEL4) { src = pose; dst = poseh; j = idx - NEL4; }
    else return;
    float4 v = reinterpret_cast<const float4*>(src)[j];
    __half2 h0 = __floats2half2_rn(v.x, v.y);
    __half2 h1 = __floats2half2_rn(v.z, v.w);
    reinterpret_cast<uint2*>(dst)[j] = make_uint2(
        *reinterpret_cast<uint32_t*>(&h0), *reinterpret_cast<uint32_t*>(&h1));
}

// ---------------------------------------------------------------------------
// Weight transpose -> half: WqT/WkT/WvT [512,400]; WpT [400,512]
// ---------------------------------------------------------------------------
__global__ __launch_bounds__(256)
void transpose_w(const float* __restrict__ Wq, const float* __restrict__ Wk,
                 const float* __restrict__ Wv, const float* __restrict__ Wp,
                 __half* __restrict__ out)
{
    const int SZ = 512 * 400;
    int idx = blockIdx.x * 256 + threadIdx.x;
    if (idx < 3 * SZ) {
        int w = idx / SZ, rr = idx % SZ;
        int h = rr / 400, dd = rr % 400;
        const float* W = (w == 0) ? Wq : (w == 1) ? Wk : Wv;
        out[idx] = __float2half_rn(W[dd * 512 + h]);
    } else if (idx < 4 * SZ) {
        int rr = idx - 3 * SZ;
        int n = rr / 512, kk = rr % 512;
        out[idx] = __float2half_rn(Wp[kk * 400 + n]);
    }
}

// ---------------------------------------------------------------------------
// Row softmax: 2048 half scores -> half probs. 256 thr/row, 1 uint4 each.
// ---------------------------------------------------------------------------
__global__ __launch_bounds__(256)
void softmax_rows_kernel(const __half* __restrict__ S, __half* __restrict__ P)
{
    const uint4* row = reinterpret_cast<const uint4*>(S + (long long)blockIdx.x * SP_);
    uint4* prow = reinterpret_cast<uint4*>(P + (long long)blockIdx.x * SP_);
    const int tid = threadIdx.x;
    uint4 raw = row[tid];
    float v[8];
    {
        __half2* h = reinterpret_cast<__half2*>(&raw);
#pragma unroll
        for (int i = 0; i < 4; i++) {
            float2 f = __half22float2(h[i]);
            v[2 * i] = f.x; v[2 * i + 1] = f.y;
        }
    }
    float mx = -INFINITY;
#pragma unroll
    for (int i = 0; i < 8; i++) mx = fmaxf(mx, v[i]);
    __shared__ float red[256];
    red[tid] = mx; __syncthreads();
#pragma unroll
    for (int s = 128; s > 0; s >>= 1) {
        if (tid < s) red[tid] = fmaxf(red[tid], red[tid + s]);
        __syncthreads();
    }
    mx = red[0]; __syncthreads();
    float sum = 0.f;
#pragma unroll
    for (int i = 0; i < 8; i++) { v[i] = __expf(v[i] - mx); sum += v[i]; }
    red[tid] = sum; __syncthreads();
#pragma unroll
    for (int s = 128; s > 0; s >>= 1) {
        if (tid < s) red[tid] += red[tid + s];
        __syncthreads();
    }
    const float inv = 1.f / red[0];
    uint4 outw;
    __half2* oh = reinterpret_cast<__half2*>(&outw);
#pragma unroll
    for (int i = 0; i < 4; i++)
        oh[i] = __floats2half2_rn(v[2 * i] * inv, v[2 * i + 1] * inv);
    prow[tid] = outw;
}

// ---------------------------------------------------------------------------
// x = rgb + gate*proj ; out = LN(x)*gamma + beta
// ---------------------------------------------------------------------------
__global__ __launch_bounds__(256)
void residual_ln_kernel(const float* __restrict__ proj, const float* __restrict__ rgb,
                        const float* __restrict__ gamma, const float* __restrict__ beta,
                        const float* __restrict__ gate, float* __restrict__ out)
{
    const long long row = blockIdx.x;
    const float g = gate[0];
    const float* pr = proj + row * DIM_;
    const float* rr = rgb + row * DIM_;
    float* orow = out + row * DIM_;
    const int tid = threadIdx.x;
    const int i1 = tid + 256;
    const bool has1 = (i1 < DIM_);

    float x0 = rr[tid] + g * pr[tid];
    float x1 = has1 ? (rr[i1] + g * pr[i1]) : 0.f;

    __shared__ float rs[256], rs2[256];
    rs[tid] = x0 + x1;
    rs2[tid] = x0 * x0 + x1 * x1;
    __syncthreads();
#pragma unroll
    for (int s = 128; s > 0; s >>= 1) {
        if (tid < s) { rs[tid] += rs[tid + s]; rs2[tid] += rs2[tid + s]; }
        __syncthreads();
    }
    const float mean = rs[0] * (1.f / DIM_);
    const float var  = rs2[0] * (1.f / DIM_) - mean * mean;
    const float inv  = rsqrtf(var + 1e-5f);

    orow[tid] = (x0 - mean) * inv * gamma[tid] + beta[tid];
    if (has1) orow[i1] = (x1 - mean) * inv * gamma[i1] + beta[i1];
}

// ---------------------------------------------------------------------------
// Launch
// ---------------------------------------------------------------------------
extern "C" void kernel_launch(void* const* d_in, const int* in_sizes, int n_in,
                              void* d_out, int out_size)
{
    const float* rgb  = (const float*)d_in[0];
    const float* pose = (const float*)d_in[1];
    const float* Wq   = (const float*)d_in[2];
    const float* bq   = (const float*)d_in[3];
    const float* Wk   = (const float*)d_in[4];
    const float* bk   = (const float*)d_in[5];
    const float* Wv   = (const float*)d_in[6];
    const float* bv   = (const float*)d_in[7];
    const float* Wp   = (const float*)d_in[8];
    const float* bp   = (const float*)d_in[9];
    const float* lng  = (const float*)d_in[10];
    const float* lnb  = (const float*)d_in[11];
    const float* gate = (const float*)d_in[12];
    float* out = (float*)d_out;

    __half *q, *k, *vt, *sh, *ph, *o, *wt, *rgbh, *poseh;
    float *p;
    cudaGetSymbolAddress((void**)&q,  g_q);
    cudaGetSymbolAddress((void**)&k,  g_k);
    cudaGetSymbolAddress((void**)&vt, g_vt);
    cudaGetSymbolAddress((void**)&sh, g_sh);
    cudaGetSymbolAddress((void**)&ph, g_ph);
    cudaGetSymbolAddress((void**)&o,  g_o);
    cudaGetSymbolAddress((void**)&p,  g_p);
    cudaGetSymbolAddress((void**)&wt, g_wt);
    cudaGetSymbolAddress((void**)&rgbh,  g_rgbh);
    cudaGetSymbolAddress((void**)&poseh, g_poseh);

    const int SMEM128 = 3 * (16384 + 128 * 128);   // 96 KB
    const int SMEM256 = 3 * (16384 + 256 * 128);   // 144 KB
    cudaFuncSetAttribute(h16_mma_gemm<128,0,1>, cudaFuncAttributeMaxDynamicSharedMemorySize, SMEM128);
    cudaFuncSetAttribute(h16_mma_gemm<128,0,0>, cudaFuncAttributeMaxDynamicSharedMemorySize, SMEM128);
    cudaFuncSetAttribute(h16_mma_gemm<128,2,1>, cudaFuncAttributeMaxDynamicSharedMemorySize, SMEM128);
    cudaFuncSetAttribute(h16_mma_gemm<256,0,1>, cudaFuncAttributeMaxDynamicSharedMemorySize, SMEM256);

    const int WSZ = 512 * 400;

    // 0. prep
    {
        long long n4 = 2LL * MROWS * DIM_ / 4;
        prep_half<<<(unsigned)((n4 + 255) / 256), 256>>>(rgb, pose, rgbh, poseh);
        transpose_w<<<(4 * WSZ + 255) / 256, 256>>>(Wq, Wk, Wv, Wp, wt);
    }

    // 1. q projection: [65536,400]@[400,512] -> half
    {
        dim3 grid(4, MROWS / 128, 1);
        h16_mma_gemm<128,0,1><<<grid, 256, SMEM128>>>(
            rgbh, wt, bq, nullptr, q, nullptr, HID_, DIM_, 0, 0, 0, 1.f);
    }
    // 2. fused k|v projection: B = [WkT;WvT] (1024x400); k plain, v -> vT
    {
        dim3 grid(8, MROWS / 128, 1);
        h16_mma_gemm<128,2,1><<<grid, 256, SMEM128>>>(
            poseh, wt + WSZ, bk, bv, k, vt, 1024, DIM_, 0, 0, 0, 1.f);
    }
    // 3. scores = q @ k^T / sqrt(512) -> half, batched
    {
        dim3 grid(SP_ / 256, SR_ / 128, B_);
        h16_mma_gemm<256,0,1><<<grid, 256, SMEM256>>>(
            q, k, nullptr, nullptr, sh, nullptr, SP_, HID_,
            (long long)SR_ * HID_, (long long)SP_ * HID_,
            (long long)SR_ * SP_, 0.044194173824159216f);
    }
    // 4. softmax half -> half
    softmax_rows_kernel<<<B_ * SR_, 256>>>(sh, ph);

    // 5. O = probs @ v (B = vT [H][Sp]) -> half, batched
    {
        dim3 grid(HID_ / 256, SR_ / 128, B_);
        h16_mma_gemm<256,0,1><<<grid, 256, SMEM256>>>(
            ph, vt, nullptr, nullptr, o, nullptr, HID_, SP_,
            (long long)SR_ * SP_, (long long)HID_ * SP_,
            (long long)SR_ * HID_, 1.f);
    }
    // 6. proj = O @ Wp + bp -> fp32
    {
        dim3 grid((DIM_ + 127) / 128, MROWS / 128, 1);
        h16_mma_gemm<128,0,0><<<grid, 256, SMEM128>>>(
            o, wt + 3 * WSZ, bp, nullptr, p, nullptr, DIM_, HID_, 0, 0, 0, 1.f);
    }
    // 7. residual + LayerNorm
    residual_ln_kernel<<<MROWS, 256>>>(p, rgb, lng, lnb, gate, out);
}

// round 8
// speedup vs baseline: 1.0589x; 1.0589x over previous
#include <cuda_runtime.h>
#include <cuda_fp16.h>
#include <cstdint>
#include <math.h>

// ---------------------------------------------------------------------------
// CrossModalFusion, fp16 mma.sync (m16n8k16, f32 acc).
// R8: BN=128/2-CTA everywhere, fused k|v, half scores, shuffle softmax.
// B=32, Sr=Sp=2048, D=400, H=512
// ---------------------------------------------------------------------------
#define B_   32
#define SR_  2048
#define SP_  2048
#define DIM_ 400
#define HID_ 512
#define MROWS (B_ * SR_)          // 65536

__device__ __half g_q [(size_t)MROWS * HID_];
__device__ __half g_k [(size_t)MROWS * HID_];
__device__ __half g_vt[(size_t)MROWS * HID_];     // [B][H][Sp]
__device__ __half g_sh[(size_t)B_ * SR_ * SP_];   // scores (half)
__device__ __half g_ph[(size_t)B_ * SR_ * SP_];   // probs (half)
__device__ __half g_o [(size_t)MROWS * HID_];
__device__ float  g_p [(size_t)MROWS * DIM_];
__device__ __half g_wt[4 * 512 * 400];            // WqT | WkT | WvT | WpT
__device__ __half g_rgbh [(size_t)MROWS * DIM_];
__device__ __half g_poseh[(size_t)MROWS * DIM_];

__device__ __forceinline__ uint32_t smem_u32(const void* p) {
    uint32_t a;
    asm("{ .reg .u64 t; cvta.to.shared.u64 t, %1; cvt.u32.u64 %0, t; }" : "=r"(a) : "l"(p));
    return a;
}
__device__ __forceinline__ void cp16(uint32_t dst, const void* src, int bytes) {
    asm volatile("cp.async.cg.shared.global [%0], [%1], 16, %2;"
                 :: "r"(dst), "l"(src), "r"(bytes));
}
#define LDSM_X4(r0, r1, r2, r3, addr)                                         \
    asm volatile("ldmatrix.sync.aligned.m8n8.x4.shared.b16 {%0,%1,%2,%3}, [%4];" \
                 : "=r"(r0), "=r"(r1), "=r"(r2), "=r"(r3) : "r"(addr))

#define MMA_F16(c, a0, a1, a2, a3, b0, b1)                                    \
    asm volatile("mma.sync.aligned.m16n8k16.row.col.f32.f16.f16.f32 "         \
                 "{%0,%1,%2,%3}, {%4,%5,%6,%7}, {%8,%9}, {%0,%1,%2,%3};"      \
                 : "+f"((c)[0]), "+f"((c)[1]), "+f"((c)[2]), "+f"((c)[3])     \
                 : "r"(a0), "r"(a1), "r"(a2), "r"(a3), "r"(b0), "r"(b1))

// ---------------------------------------------------------------------------
// fp16 GEMM: C[M,N] = alpha*A[M,K]@B[N,K]^T (+bias), f32 acc.
// CTA tile 128x128, 8 warps (warp tile 64x32), BK=64 halves, 3-stage cp.async.
// MODE 0: plain store (OUT_HALF: half2 vs float2).
// MODE 2: fused k|v — n0<512: k store (ld 512, bias); n0>=512: vT via smem (bias2).
// ---------------------------------------------------------------------------
template <int MODE, int OUT_HALF>
__global__ __launch_bounds__(256, 2)
void h16_mma_gemm(const __half* __restrict__ A, const __half* __restrict__ Bm,
                  const float* __restrict__ bias, const float* __restrict__ bias2,
                  void* __restrict__ Cv, __half* __restrict__ C2,
                  int N, int K,
                  long long sA, long long sB, long long sC, float alpha)
{
    extern __shared__ char smem[];
    const uint32_t sb = smem_u32(smem);
    const int tid = threadIdx.x;
    const int wid = tid >> 5, lane = tid & 31;
    const int warp_m = wid & 1;
    const int warp_n = wid >> 1;

    A  += (long long)blockIdx.z * sA;
    Bm += (long long)blockIdx.z * sB;
    const int m0 = blockIdx.y * 128;
    const int n0 = blockIdx.x * 128;
    const int KT = (K + 63) >> 6;

    auto load_stage = [&](int kt, int s) {
        const int k0 = kt << 6;
        const uint32_t base = sb + (uint32_t)s * 32768u;
#pragma unroll
        for (int i = 0; i < 4; i++) {
            int e = tid + (i << 8);
            int row = e >> 3, c = e & 7;
            int kk = k0 + (c << 3);
            uint32_t off = (uint32_t)(row * 128) + (uint32_t)((c ^ (row & 7)) << 4);
            const bool kin = kk < K;
            const __half* ga = A + (long long)(m0 + row) * K + kk;
            cp16(base + off, ga, kin ? 16 : 0);
            const bool bin = kin && (n0 + row) < N;
            const __half* gb = Bm + (long long)(n0 + row) * K + kk;
            cp16(base + 16384u + off, bin ? gb : Bm, bin ? 16 : 0);
        }
        asm volatile("cp.async.commit_group;" ::: "memory");
    };

    float acc[4][4][4];
#pragma unroll
    for (int i = 0; i < 4; i++)
#pragma unroll
        for (int j = 0; j < 4; j++)
#pragma unroll
            for (int k = 0; k < 4; k++) acc[i][j][k] = 0.f;

    const int t = lane >> 3, r = lane & 7;
    const uint32_t a_row = (uint32_t)(warp_m * 64 + (t & 1) * 8 + r);
    const uint32_t b_row = (uint32_t)(warp_n * 32 + (t & 1) * 8 + r);
    const uint32_t chb   = (uint32_t)(t >> 1);

    load_stage(0, 0);
    if (KT > 1) load_stage(1, 1);

    for (int kt = 0; kt < KT; kt++) {
        if (kt + 1 < KT) asm volatile("cp.async.wait_group 1;" ::: "memory");
        else             asm volatile("cp.async.wait_group 0;" ::: "memory");
        __syncthreads();
        if (kt + 2 < KT) load_stage(kt + 2, (kt + 2) % 3);

        const uint32_t baseA = sb + (uint32_t)(kt % 3) * 32768u;
        const uint32_t baseB = baseA + 16384u;

#pragma unroll
        for (int ks = 0; ks < 4; ks++) {
            uint32_t a[4][4], b[2][4];
#pragma unroll
            for (int mi = 0; mi < 4; mi++) {
                uint32_t addr = baseA + (a_row + mi * 16) * 128u
                              + ((((ks * 2) + chb) ^ (uint32_t)r) << 4);
                LDSM_X4(a[mi][0], a[mi][1], a[mi][2], a[mi][3], addr);
            }
#pragma unroll
            for (int j = 0; j < 2; j++) {
                uint32_t addr = baseB + (b_row + j * 16) * 128u
                              + ((((ks * 2) + chb) ^ (uint32_t)r) << 4);
                LDSM_X4(b[j][0], b[j][1], b[j][2], b[j][3], addr);
            }
#pragma unroll
            for (int mi = 0; mi < 4; mi++)
#pragma unroll
                for (int ni = 0; ni < 4; ni++)
                    MMA_F16(acc[mi][ni], a[mi][0], a[mi][1], a[mi][2], a[mi][3],
                            b[ni >> 1][ni & 1], b[ni >> 1][(ni & 1) + 2]);
        }
    }

    const int m_base_l = warp_m * 64;
    const int n_base_l = warp_n * 32;
    const int row_in = lane >> 2;
    const int col_in = (lane & 3) * 2;

    const bool k_side = (MODE != 2) || (n0 < 512);

    if (MODE == 0 || k_side) {
        const int ldC = (MODE == 2) ? 512 : N;
#pragma unroll
        for (int mi = 0; mi < 4; mi++) {
            const int gm0 = m0 + m_base_l + mi * 16 + row_in;
#pragma unroll
            for (int ni = 0; ni < 4; ni++) {
                const int gn = n0 + n_base_l + ni * 8 + col_in;
                if (gn < N) {
                    float b0 = bias ? __ldg(&bias[gn]) : 0.f;
                    float b1 = bias ? __ldg(&bias[gn + 1]) : 0.f;
                    float v00 = acc[mi][ni][0] * alpha + b0;
                    float v01 = acc[mi][ni][1] * alpha + b1;
                    float v10 = acc[mi][ni][2] * alpha + b0;
                    float v11 = acc[mi][ni][3] * alpha + b1;
                    if (OUT_HALF) {
                        __half* C = (__half*)Cv + (long long)blockIdx.z * sC;
                        *reinterpret_cast<__half2*>(&C[(long long)gm0 * ldC + gn]) =
                            __floats2half2_rn(v00, v01);
                        *reinterpret_cast<__half2*>(&C[(long long)(gm0 + 8) * ldC + gn]) =
                            __floats2half2_rn(v10, v11);
                    } else {
                        float* C = (float*)Cv + (long long)blockIdx.z * sC;
                        *reinterpret_cast<float2*>(&C[(long long)gm0 * ldC + gn]) =
                            make_float2(v00, v01);
                        *reinterpret_cast<float2*>(&C[(long long)(gm0 + 8) * ldC + gn]) =
                            make_float2(v10, v11);
                    }
                }
            }
        }
    } else {
        // v side: vT[b][h][p], h = gn - 512. Stage [n][m] half tile in smem.
        __syncthreads();
        __half* sm = reinterpret_cast<__half*>(smem);
        const int PAD = 136;
        const int h0 = n0 - 512;
#pragma unroll
        for (int mi = 0; mi < 4; mi++) {
            const int ml = m_base_l + mi * 16 + row_in;
#pragma unroll
            for (int ni = 0; ni < 4; ni++) {
                const int nl = n_base_l + ni * 8 + col_in;
                float b0 = bias2 ? __ldg(&bias2[h0 + nl]) : 0.f;
                float b1 = bias2 ? __ldg(&bias2[h0 + nl + 1]) : 0.f;
                sm[nl * PAD + ml]           = __float2half_rn(acc[mi][ni][0] + b0);
                sm[(nl + 1) * PAD + ml]     = __float2half_rn(acc[mi][ni][1] + b1);
                sm[nl * PAD + ml + 8]       = __float2half_rn(acc[mi][ni][2] + b0);
                sm[(nl + 1) * PAD + ml + 8] = __float2half_rn(acc[mi][ni][3] + b1);
            }
        }
        __syncthreads();
        const long long obase = ((long long)(m0 >> 11) << 20) + (m0 & 2047);
#pragma unroll
        for (int pass = 0; pass < 8; pass++) {
            int chunk = pass * 256 + tid;
            int n = chunk >> 4;
            int mc = (chunk & 15) << 3;
            uint4 v = *reinterpret_cast<uint4*>(&sm[n * PAD + mc]);
            *reinterpret_cast<uint4*>(&C2[obase + ((long long)(h0 + n) << 11) + mc]) = v;
        }
    }
}

// ---------------------------------------------------------------------------
// rgb & pose -> half copies
// ---------------------------------------------------------------------------
__global__ __launch_bounds__(256)
void prep_half(const float* __restrict__ rgb, const float* __restrict__ pose,
               __half* __restrict__ rgbh, __half* __restrict__ poseh)
{
    const long long NEL4 = (long long)MROWS * DIM_ / 4;
    long long idx = (long long)blockIdx.x * 256 + threadIdx.x;
    const float* src; __half* dst; long long j;
    if (idx < NEL4)          { src = rgb;  dst = rgbh;  j = idx; }
    else if (idx < 2 * NEL4) { src = pose; dst = poseh; j = idx - NEL4; }
    else return;
    float4 v = reinterpret_cast<const float4*>(src)[j];
    __half2 h0 = __floats2half2_rn(v.x, v.y);
    __half2 h1 = __floats2half2_rn(v.z, v.w);
    reinterpret_cast<uint2*>(dst)[j] = make_uint2(
        *reinterpret_cast<uint32_t*>(&h0), *reinterpret_cast<uint32_t*>(&h1));
}

// ---------------------------------------------------------------------------
// Weight transpose -> half: WqT/WkT/WvT [512,400]; WpT [400,512]
// ---------------------------------------------------------------------------
__global__ __launch_bounds__(256)
void transpose_w(const float* __restrict__ Wq, const float* __restrict__ Wk,
                 const float* __restrict__ Wv, const float* __restrict__ Wp,
                 __half* __restrict__ out)
{
    const int SZ = 512 * 400;
    int idx = blockIdx.x * 256 + threadIdx.x;
    if (idx < 3 * SZ) {
        int w = idx / SZ, rr = idx % SZ;
        int h = rr / 400, dd = rr % 400;
        const float* W = (w == 0) ? Wq : (w == 1) ? Wk : Wv;
        out[idx] = __float2half_rn(W[dd * 512 + h]);
    } else if (idx < 4 * SZ) {
        int rr = idx - 3 * SZ;
        int n = rr / 512, kk = rr % 512;
        out[idx] = __float2half_rn(Wp[kk * 400 + n]);
    }
}

// ---------------------------------------------------------------------------
// Row softmax: 2048 half -> half. 256 thr/row, warp-shuffle reductions.
// ---------------------------------------------------------------------------
__global__ __launch_bounds__(256)
void softmax_rows_kernel(const __half* __restrict__ S, __half* __restrict__ P)
{
    const uint4* row = reinterpret_cast<const uint4*>(S + (long long)blockIdx.x * SP_);
    uint4* prow = reinterpret_cast<uint4*>(P + (long long)blockIdx.x * SP_);
    const int tid = threadIdx.x;
    const int wid = tid >> 5, lane = tid & 31;

    uint4 raw = row[tid];
    float v[8];
    {
        __half2* h = reinterpret_cast<__half2*>(&raw);
#pragma unroll
        for (int i = 0; i < 4; i++) {
            float2 f = __half22float2(h[i]);
            v[2 * i] = f.x; v[2 * i + 1] = f.y;
        }
    }
    float mx = v[0];
#pragma unroll
    for (int i = 1; i < 8; i++) mx = fmaxf(mx, v[i]);
#pragma unroll
    for (int s = 16; s > 0; s >>= 1)
        mx = fmaxf(mx, __shfl_xor_sync(0xFFFFFFFFu, mx, s));

    __shared__ float red[8];
    if (lane == 0) red[wid] = mx;
    __syncthreads();
    {
        float m = red[lane & 7];
#pragma unroll
        for (int s = 4; s > 0; s >>= 1)
            m = fmaxf(m, __shfl_xor_sync(0xFFFFFFFFu, m, s));
        mx = m;
    }

    float sum = 0.f;
#pragma unroll
    for (int i = 0; i < 8; i++) { v[i] = __expf(v[i] - mx); sum += v[i]; }
#pragma unroll
    for (int s = 16; s > 0; s >>= 1)
        sum += __shfl_xor_sync(0xFFFFFFFFu, sum, s);
    __syncthreads();           // red reuse guard
    if (lane == 0) red[wid] = sum;
    __syncthreads();
    {
        float sm = red[lane & 7];
#pragma unroll
        for (int s = 4; s > 0; s >>= 1)
            sm += __shfl_xor_sync(0xFFFFFFFFu, sm, s);
        sum = sm;
    }
    const float inv = 1.f / sum;

    uint4 outw;
    __half2* oh = reinterpret_cast<__half2*>(&outw);
#pragma unroll
    for (int i = 0; i < 4; i++)
        oh[i] = __floats2half2_rn(v[2 * i] * inv, v[2 * i + 1] * inv);
    prow[tid] = outw;
}

// ---------------------------------------------------------------------------
// x = rgb + gate*proj ; out = LN(x)*gamma + beta
// ---------------------------------------------------------------------------
__global__ __launch_bounds__(256)
void residual_ln_kernel(const float* __restrict__ proj, const float* __restrict__ rgb,
                        const float* __restrict__ gamma, const float* __restrict__ beta,
                        const float* __restrict__ gate, float* __restrict__ out)
{
    const long long row = blockIdx.x;
    const float g = gate[0];
    const float* pr = proj + row * DIM_;
    const float* rr = rgb + row * DIM_;
    float* orow = out + row * DIM_;
    const int tid = threadIdx.x;
    const int i1 = tid + 256;
    const bool has1 = (i1 < DIM_);

    float x0 = rr[tid] + g * pr[tid];
    float x1 = has1 ? (rr[i1] + g * pr[i1]) : 0.f;

    __shared__ float rs[256], rs2[256];
    rs[tid] = x0 + x1;
    rs2[tid] = x0 * x0 + x1 * x1;
    __syncthreads();
#pragma unroll
    for (int s = 128; s > 0; s >>= 1) {
        if (tid < s) { rs[tid] += rs[tid + s]; rs2[tid] += rs2[tid + s]; }
        __syncthreads();
    }
    const float mean = rs[0] * (1.f / DIM_);
    const float var  = rs2[0] * (1.f / DIM_) - mean * mean;
    const float inv  = rsqrtf(var + 1e-5f);

    orow[tid] = (x0 - mean) * inv * gamma[tid] + beta[tid];
    if (has1) orow[i1] = (x1 - mean) * inv * gamma[i1] + beta[i1];
}

// ---------------------------------------------------------------------------
// Launch
// ---------------------------------------------------------------------------
extern "C" void kernel_launch(void* const* d_in, const int* in_sizes, int n_in,
                              void* d_out, int out_size)
{
    const float* rgb  = (const float*)d_in[0];
    const float* pose = (const float*)d_in[1];
    const float* Wq   = (const float*)d_in[2];
    const float* bq   = (const float*)d_in[3];
    const float* Wk   = (const float*)d_in[4];
    const float* bk   = (const float*)d_in[5];
    const float* Wv   = (const float*)d_in[6];
    const float* bv   = (const float*)d_in[7];
    const float* Wp   = (const float*)d_in[8];
    const float* bp   = (const float*)d_in[9];
    const float* lng  = (const float*)d_in[10];
    const float* lnb  = (const float*)d_in[11];
    const float* gate = (const float*)d_in[12];
    float* out = (float*)d_out;

    __half *q, *k, *vt, *sh, *ph, *o, *wt, *rgbh, *poseh;
    float *p;
    cudaGetSymbolAddress((void**)&q,  g_q);
    cudaGetSymbolAddress((void**)&k,  g_k);
    cudaGetSymbolAddress((void**)&vt, g_vt);
    cudaGetSymbolAddress((void**)&sh, g_sh);
    cudaGetSymbolAddress((void**)&ph, g_ph);
    cudaGetSymbolAddress((void**)&o,  g_o);
    cudaGetSymbolAddress((void**)&p,  g_p);
    cudaGetSymbolAddress((void**)&wt, g_wt);
    cudaGetSymbolAddress((void**)&rgbh,  g_rgbh);
    cudaGetSymbolAddress((void**)&poseh, g_poseh);

    const int SMEM = 3 * 32768;        // 96 KB
    cudaFuncSetAttribute(h16_mma_gemm<0,1>, cudaFuncAttributeMaxDynamicSharedMemorySize, SMEM);
    cudaFuncSetAttribute(h16_mma_gemm<0,0>, cudaFuncAttributeMaxDynamicSharedMemorySize, SMEM);
    cudaFuncSetAttribute(h16_mma_gemm<2,1>, cudaFuncAttributeMaxDynamicSharedMemorySize, SMEM);

    const int WSZ = 512 * 400;

    // 0. prep
    {
        long long n4 = 2LL * MROWS * DIM_ / 4;
        prep_half<<<(unsigned)((n4 + 255) / 256), 256>>>(rgb, pose, rgbh, poseh);
        transpose_w<<<(4 * WSZ + 255) / 256, 256>>>(Wq, Wk, Wv, Wp, wt);
    }

    // 1. q projection -> half
    {
        dim3 grid(4, MROWS / 128, 1);
        h16_mma_gemm<0,1><<<grid, 256, SMEM>>>(
            rgbh, wt, bq, nullptr, q, nullptr, HID_, DIM_, 0, 0, 0, 1.f);
    }
    // 2. fused k|v projection: B = [WkT;WvT] (1024x400); k plain, v -> vT
    {
        dim3 grid(8, MROWS / 128, 1);
        h16_mma_gemm<2,1><<<grid, 256, SMEM>>>(
            poseh, wt + WSZ, bk, bv, k, vt, 1024, DIM_, 0, 0, 0, 1.f);
    }
    // 3. scores = q @ k^T / sqrt(512) -> half, batched
    {
        dim3 grid(SP_ / 128, SR_ / 128, B_);
        h16_mma_gemm<0,1><<<grid, 256, SMEM>>>(
            q, k, nullptr, nullptr, sh, nullptr, SP_, HID_,
            (long long)SR_ * HID_, (long long)SP_ * HID_,
            (long long)SR_ * SP_, 0.044194173824159216f);
    }
    // 4. softmax half -> half
    softmax_rows_kernel<<<B_ * SR_, 256>>>(sh, ph);

    // 5. O = probs @ v (B = vT [H][Sp]) -> half, batched
    {
        dim3 grid(HID_ / 128, SR_ / 128, B_);
        h16_mma_gemm<0,1><<<grid, 256, SMEM>>>(
            ph, vt, nullptr, nullptr, o, nullptr, HID_, SP_,
            (long long)SR_ * SP_, (long long)HID_ * SP_,
            (long long)SR_ * HID_, 1.f);
    }
    // 6. proj = O @ Wp + bp -> fp32
    {
        dim3 grid((DIM_ + 127) / 128, MROWS / 128, 1);
        h16_mma_gemm<0,0><<<grid, 256, SMEM>>>(
            o, wt + 3 * WSZ, bp, nullptr, p, nullptr, DIM_, HID_, 0, 0, 0, 1.f);
    }
    // 7. residual + LayerNorm
    residual_ln_kernel<<<MROWS, 256>>>(p, rgb, lng, lnb, gate, out);
}